// round 12
// baseline (speedup 1.0000x reference)
#include <cuda_runtime.h>

// SWT level-1 (db2, norm=True) along channel axis with periodic wrap.
// x:   [B=8, C=64, H=128, W=128] f32
// out: [B=8, 2C=128, H=128, W=128] f32  (cA in [0,64), cD in [64,128))
//
// cA[c] = lo0*x[c+2] + lo1*x[c+1] + lo2*x[c] + lo3*x[c-1]   (mod 64)
// cD[c] = hi0*x[c+2] + hi1*x[c+1] + hi2*x[c] + hi3*x[c-1]
//
// R11: exact R8 config (best, 14.53us) with ONE change: default evict_normal
// stores instead of __stcs. Working set (33.5MB in + 67MB out = 100.5MB) fits
// in the 126MB L2, so under graph-replay steady state the output lines should
// stay L2-resident and dirty -> replays re-write them as L2 hits, DRAM drain
// disappears, kernel becomes L2-BW bound (~10.5us floor) instead of
// DRAM-write-drain bound (~14.5us).

#define HW4 4096  // (128*128)/4 float4 per channel plane
#define CHUNK 4

__global__ __launch_bounds__(256, 6)
void swt_db2_kernel(const float4* __restrict__ x, float4* __restrict__ out) {
    const float INV_SQRT2 = 0.70710678118654752440f;
    const float lo0 = -0.12940952255092145f * INV_SQRT2;  // * x[c+2]
    const float lo1 =  0.22414386804185735f * INV_SQRT2;  // * x[c+1]
    const float lo2 =  0.83651630373746900f * INV_SQRT2;  // * x[c]
    const float lo3 =  0.48296291314469025f * INV_SQRT2;  // * x[c-1]
    const float hi0 = -0.48296291314469025f * INV_SQRT2;
    const float hi1 =  0.83651630373746900f * INV_SQRT2;
    const float hi2 = -0.22414386804185735f * INV_SQRT2;
    const float hi3 = -0.12940952255092145f * INV_SQRT2;

    int t = blockIdx.x * blockDim.x + threadIdx.x;   // 0 .. 524287
    int s     = t & 4095;          // float4 index within HxW plane
    int chunk = (t >> 12) & 15;    // which 4-channel chunk
    int b     = t >> 16;           // batch
    int c0    = chunk << 2;        // first output channel of this chunk

    const float4* xin = x   + ((size_t)b << 18) + s;                     // b*64*4096
    float4*       oA  = out + ((size_t)b << 19) + (size_t)c0 * HW4 + s;  // b*128*4096
    float4*       oD  = oA + (size_t)64 * HW4;

    // Front-load the 7 planes c0-1 .. c0+5 (mod 64): 7 independent LDG.128.
    float4 w[CHUNK + 3];
#pragma unroll
    for (int k = 0; k < CHUNK + 3; ++k) {
        int c = (c0 + k + 63) & 63;   // c0-1+k, wrapped
        w[k] = xin[(size_t)c * HW4];
    }

#pragma unroll
    for (int i = 0; i < CHUNK; ++i) {
        float4 wa = w[i], wb = w[i + 1], wc = w[i + 2], wd = w[i + 3];
        float4 A, D;
        A.x = fmaf(lo0, wd.x, fmaf(lo1, wc.x, fmaf(lo2, wb.x, lo3 * wa.x)));
        A.y = fmaf(lo0, wd.y, fmaf(lo1, wc.y, fmaf(lo2, wb.y, lo3 * wa.y)));
        A.z = fmaf(lo0, wd.z, fmaf(lo1, wc.z, fmaf(lo2, wb.z, lo3 * wa.z)));
        A.w = fmaf(lo0, wd.w, fmaf(lo1, wc.w, fmaf(lo2, wb.w, lo3 * wa.w)));
        D.x = fmaf(hi0, wd.x, fmaf(hi1, wc.x, fmaf(hi2, wb.x, hi3 * wa.x)));
        D.y = fmaf(hi0, wd.y, fmaf(hi1, wc.y, fmaf(hi2, wb.y, hi3 * wa.y)));
        D.z = fmaf(hi0, wd.z, fmaf(hi1, wc.z, fmaf(hi2, wb.z, hi3 * wa.z)));
        D.w = fmaf(hi0, wd.w, fmaf(hi1, wc.w, fmaf(hi2, wb.w, hi3 * wa.w)));

        // Default evict_normal stores: output lines stay resident+dirty in L2
        // across graph replays (working set < L2 capacity).
        oA[(size_t)i * HW4] = A;
        oD[(size_t)i * HW4] = D;
    }
}

extern "C" void kernel_launch(void* const* d_in, const int* in_sizes, int n_in,
                              void* d_out, int out_size) {
    const float4* x = (const float4*)d_in[0];
    float4* out = (float4*)d_out;
    // 8 batches * 16 chunks * 4096 spatial float4 = 524288 threads
    swt_db2_kernel<<<2048, 256>>>(x, out);
}

// round 13
// speedup vs baseline: 1.0168x; 1.0168x over previous
#include <cuda_runtime.h>

// SWT level-1 (db2, norm=True) along channel axis with periodic wrap.
// x:   [B=8, C=64, H=128, W=128] f32
// out: [B=8, 2C=128, H=128, W=128] f32  (cA in [0,64), cD in [64,128))
//
// cA[c] = lo0*x[c+2] + lo1*x[c+1] + lo2*x[c] + lo3*x[c-1]   (mod 64)
// cD[c] = hi0*x[c+2] + hi1*x[c+1] + hi2*x[c] + hi3*x[c-1]
//
// R12: R8 config (best, 14.53us) with ONE change: __stwt (write-through)
// stores instead of __stcs. R11 proved output must stream to DRAM and that
// polluting L2 with output costs ~3us. __stwt goes one step further than
// __stcs: no L2 allocation at all for output lines -> single pass through
// LTS, full 126MB L2 left for the 33.5MB input (reads become pure L2 hits
// in replay steady state). Binding resource = DRAM write drain.

#define HW4 4096  // (128*128)/4 float4 per channel plane
#define CHUNK 4

__global__ __launch_bounds__(256, 6)
void swt_db2_kernel(const float4* __restrict__ x, float4* __restrict__ out) {
    const float INV_SQRT2 = 0.70710678118654752440f;
    const float lo0 = -0.12940952255092145f * INV_SQRT2;  // * x[c+2]
    const float lo1 =  0.22414386804185735f * INV_SQRT2;  // * x[c+1]
    const float lo2 =  0.83651630373746900f * INV_SQRT2;  // * x[c]
    const float lo3 =  0.48296291314469025f * INV_SQRT2;  // * x[c-1]
    const float hi0 = -0.48296291314469025f * INV_SQRT2;
    const float hi1 =  0.83651630373746900f * INV_SQRT2;
    const float hi2 = -0.22414386804185735f * INV_SQRT2;
    const float hi3 = -0.12940952255092145f * INV_SQRT2;

    int t = blockIdx.x * blockDim.x + threadIdx.x;   // 0 .. 524287
    int s     = t & 4095;          // float4 index within HxW plane
    int chunk = (t >> 12) & 15;    // which 4-channel chunk
    int b     = t >> 16;           // batch
    int c0    = chunk << 2;        // first output channel of this chunk

    const float4* xin = x   + ((size_t)b << 18) + s;                     // b*64*4096
    float4*       oA  = out + ((size_t)b << 19) + (size_t)c0 * HW4 + s;  // b*128*4096
    float4*       oD  = oA + (size_t)64 * HW4;

    // Front-load the 7 planes c0-1 .. c0+5 (mod 64): 7 independent LDG.128.
    float4 w[CHUNK + 3];
#pragma unroll
    for (int k = 0; k < CHUNK + 3; ++k) {
        int c = (c0 + k + 63) & 63;   // c0-1+k, wrapped
        w[k] = xin[(size_t)c * HW4];
    }

#pragma unroll
    for (int i = 0; i < CHUNK; ++i) {
        float4 wa = w[i], wb = w[i + 1], wc = w[i + 2], wd = w[i + 3];
        float4 A, D;
        A.x = fmaf(lo0, wd.x, fmaf(lo1, wc.x, fmaf(lo2, wb.x, lo3 * wa.x)));
        A.y = fmaf(lo0, wd.y, fmaf(lo1, wc.y, fmaf(lo2, wb.y, lo3 * wa.y)));
        A.z = fmaf(lo0, wd.z, fmaf(lo1, wc.z, fmaf(lo2, wb.z, lo3 * wa.z)));
        A.w = fmaf(lo0, wd.w, fmaf(lo1, wc.w, fmaf(lo2, wb.w, lo3 * wa.w)));
        D.x = fmaf(hi0, wd.x, fmaf(hi1, wc.x, fmaf(hi2, wb.x, hi3 * wa.x)));
        D.y = fmaf(hi0, wd.y, fmaf(hi1, wc.y, fmaf(hi2, wb.y, hi3 * wa.y)));
        D.z = fmaf(hi0, wd.z, fmaf(hi1, wc.z, fmaf(hi2, wb.z, hi3 * wa.z)));
        D.w = fmaf(hi0, wd.w, fmaf(hi1, wc.w, fmaf(hi2, wb.w, hi3 * wa.w)));

        // Write-through streaming stores: no L2 allocation for output,
        // single LTS pass, L2 stays dedicated to the input planes.
        __stwt(&oA[(size_t)i * HW4], A);
        __stwt(&oD[(size_t)i * HW4], D);
    }
}

extern "C" void kernel_launch(void* const* d_in, const int* in_sizes, int n_in,
                              void* d_out, int out_size) {
    const float4* x = (const float4*)d_in[0];
    float4* out = (float4*)d_out;
    // 8 batches * 16 chunks * 4096 spatial float4 = 524288 threads
    swt_db2_kernel<<<2048, 256>>>(x, out);
}